// round 15
// baseline (speedup 1.0000x reference)
#include <cuda_runtime.h>
#include <cuda_fp16.h>
#include <cstdint>
#include <math.h>

#define N_ 128
#define D_ 512
#define L_ 512
#define K_ 512
#define KH 256                   // half spectrum (k-mirror)
#define LH 256                   // half reduction (l-fold)
#define M_ (N_ * D_)

// ---------------- device globals (allocation-free scratch) ----------------
__device__ __half gBc[LH * KH];     // cos basis (l<256, k<256), fp16
__device__ __half gBs[LH * KH];     // sin basis
__device__ float  gCosC[LH];        // cos(c*l), l<256
__device__ float  gA1[D_];          // exp(sigma/511) * a
__device__ float  gA2[D_];          // exp(sigma/511) * (1-a)

// ---------------- helpers ----------------
__device__ __forceinline__ uint32_t smem_u32(const void* p) {
    uint32_t a;
    asm("{ .reg .u64 t; cvta.to.shared.u64 t, %1; cvt.u32.u64 %0, t; }" : "=r"(a) : "l"(p));
    return a;
}
#define CP_ASYNC16(dst, src) asm volatile("cp.async.cg.shared.global [%0], [%1], 16;" :: "r"(dst), "l"(src))
#define CP_COMMIT() asm volatile("cp.async.commit_group;" ::: "memory")

#define LDSM4(R, addr) \
    asm volatile("ldmatrix.sync.aligned.m8n8.x4.shared.b16 {%0,%1,%2,%3}, [%4];" \
        : "=r"((R)[0]), "=r"((R)[1]), "=r"((R)[2]), "=r"((R)[3]) : "r"(addr))
#define LDSM4T(R, addr) \
    asm volatile("ldmatrix.sync.aligned.m8n8.x4.trans.shared.b16 {%0,%1,%2,%3}, [%4];" \
        : "=r"((R)[0]), "=r"((R)[1]), "=r"((R)[2]), "=r"((R)[3]) : "r"(addr))

#define MMA16816(D, A, B0, B1) \
    asm volatile("mma.sync.aligned.m16n8k16.row.col.f32.f16.f16.f32 " \
        "{%0,%1,%2,%3}, {%4,%5,%6,%7}, {%8,%9}, {%0,%1,%2,%3};" \
        : "+f"((D)[0]), "+f"((D)[1]), "+f"((D)[2]), "+f"((D)[3]) \
        : "r"((A)[0]), "r"((A)[1]), "r"((A)[2]), "r"((A)[3]), "r"(B0), "r"(B1))

// ---------------- prep: basis (fp16) + window factors ----------------
__global__ void precompute_kernel(const float* __restrict__ a,
                                  const float* __restrict__ sigma) {
    const int idx = blockIdx.x * blockDim.x + threadIdx.x;
    const float c = (float)(6.283185307179586 / 511.0);
    if (idx < LH * KH) {
        const int l = idx / KH, k = idx - l * KH;
        float s, cc;
        sincosf(c * (float)(l * k), &s, &cc);
        gBc[idx] = __float2half(cc);
        gBs[idx] = __float2half(s);
    }
    if (idx < LH) gCosC[idx] = cosf(c * (float)idx);
    if (idx < D_) {
        const float es = expf(sigma[idx] * (1.0f / 511.0f));
        gA1[idx] = es * a[idx];
        gA2[idx] = es * (1.0f - a[idx]);
    }
}

// ---------------- main: fused fold + dual-GEMM + magnitude ----------------
// CTA 128(M) x 64(N); BK=16, 16 chunks; 8 warps (2Mx4N), warp tile 64x16.
// Per chunk: cp.async raw x fwd/mir fp32 slices -> fold to fp16 u,v in smem -> MMA.
#define BK 16
#define NCH (LH / BK)            // 16 chunks
#define NSTAGE 3
#define XP 80                    // x staging pitch: 16 fl = 64B + 16 pad
#define AP 48                    // A fp16 tile pitch: 16 h = 32B + 16 pad
#define BP 144                   // B pitch: 64 h = 128B + 16 pad
#define XBLK (128 * XP)          // 10240 per x block (fwd or mir)
#define BMAT (BK * BP)           // 2304 per B matrix
#define STAGE_B (2 * XBLK + 2 * BMAT)   // 25088
#define SM_COSC 0
#define SM_A    1024                     // u tile, then v tile
#define AMAT (128 * AP)                  // 6144
#define SM_STG  (SM_A + 2 * AMAT)        // 13312
#define SMEM_TOTAL (SM_STG + NSTAGE * STAGE_B)  // 88576 -> 2 CTAs/SM

__device__ __forceinline__ void load_chunk(uint32_t stg, const float* __restrict__ x,
                                           int row0, int col0, int c, int tid) {
    // x fwd: 128 rows x 4 (16B units) = 512 -> 2/thread ; x mir same
#pragma unroll
    for (int p = 0; p < 2; ++p) {
        const int u = tid + p * 256;
        const int r = u >> 2;
        const int cu = u & 3;
        const float* srcF = x + (size_t)(row0 + r) * L_ + c * BK + cu * 4;
        const float* srcM = x + (size_t)(row0 + r) * L_ + (496 - c * BK) + cu * 4;
        CP_ASYNC16(stg + r * XP + cu * 16, srcF);
        CP_ASYNC16(stg + XBLK + r * XP + cu * 16, srcM);
    }
    // B: 2 mats x 16 rows x 8 units = 256 -> 1/thread
    {
        const int mat = tid >> 7;
        const int r = (tid >> 3) & 15;
        const int cu = tid & 7;
        const __half* g = mat ? gBs : gBc;
        const __half* src = g + (size_t)(c * BK + r) * KH + col0 + cu * 8;
        CP_ASYNC16(stg + 2 * XBLK + mat * BMAT + r * BP + cu * 16, src);
    }
}

__global__ __launch_bounds__(256, 2)
void spectro_fused_kernel(const float* __restrict__ x, float* __restrict__ out) {
    extern __shared__ char smem[];
    const uint32_t sbase = smem_u32(smem);
    const int tid = threadIdx.x;
    const int wid = tid >> 5;
    const int lid = tid & 31;
    const int col0 = blockIdx.x * 64;    // 4 col tiles (k < 256)
    const int row0 = blockIdx.y * 128;   // 512 row tiles
    const int wm = wid >> 2;             // 0..1 (M)
    const int wn = wid & 3;              // 0..3 (N)

    // convert-role constants: each thread owns one row, 8 l-values per chunk
    const int cr   = tid & 127;          // row within tile
    const int half = tid >> 7;           // 0: l 0..7 ; 1: l 8..15 (of chunk)
    const int d    = (row0 + cr) & (D_ - 1);
    const float A1 = gA1[d];
    const float A2 = gA2[d];

    // stage cosC into smem
    if (tid < 64) {
        const float4 v = *(const float4*)(gCosC + tid * 4);
        *(float4*)(smem + SM_COSC + tid * 16) = v;
    }

    float accR[4][2][4];
    float accI[4][2][4];
#pragma unroll
    for (int mt = 0; mt < 4; ++mt)
#pragma unroll
        for (int nt = 0; nt < 2; ++nt)
#pragma unroll
            for (int j = 0; j < 4; ++j) { accR[mt][nt][j] = 0.f; accI[mt][nt][j] = 0.f; }

    const int g8 = lid >> 3;
    const int lr = lid & 7;

    // prologue: 2 chunks in flight
    load_chunk(sbase + SM_STG + 0 * STAGE_B, x, row0, col0, 0, tid);
    CP_COMMIT();
    load_chunk(sbase + SM_STG + 1 * STAGE_B, x, row0, col0, 1, tid);
    CP_COMMIT();

    for (int c = 0; c < NCH; ++c) {
        if (c + 1 < NCH) {
            asm volatile("cp.async.wait_group 1;" ::: "memory");
        } else {
            asm volatile("cp.async.wait_group 0;" ::: "memory");
        }
        __syncthreads();   // staging(c) visible; MMA(c-1) complete everywhere

        // prefetch chunk c+2 into slot (c+2)%3 == (c-1)%3 (freed: x by convert(c-1), B by MMA(c-1))
        if (c + 2 < NCH) {
            load_chunk(sbase + SM_STG + ((c + 2) % NSTAGE) * STAGE_B, x, row0, col0, c + 2, tid);
            CP_COMMIT();
        }

        // ---- fold + convert: staging fp32 -> u,v fp16 tiles ----
        {
            const uint32_t stg = sbase + SM_STG + (c % NSTAGE) * STAGE_B;
            const uint32_t fa = stg + cr * XP + half * 32;
            const uint32_t ma = stg + XBLK + cr * XP + (1 - half) * 32;
            float4 f0, f1, w0, w1;
            asm volatile("ld.shared.v4.f32 {%0,%1,%2,%3}, [%4];"
                         : "=f"(f0.x), "=f"(f0.y), "=f"(f0.z), "=f"(f0.w) : "r"(fa));
            asm volatile("ld.shared.v4.f32 {%0,%1,%2,%3}, [%4];"
                         : "=f"(f1.x), "=f"(f1.y), "=f"(f1.z), "=f"(f1.w) : "r"(fa + 16));
            asm volatile("ld.shared.v4.f32 {%0,%1,%2,%3}, [%4];"
                         : "=f"(w0.x), "=f"(w0.y), "=f"(w0.z), "=f"(w0.w) : "r"(ma));
            asm volatile("ld.shared.v4.f32 {%0,%1,%2,%3}, [%4];"
                         : "=f"(w1.x), "=f"(w1.y), "=f"(w1.z), "=f"(w1.w) : "r"(ma + 16));
            // mirror values reversed: m[i] = window[7-i], window = (w0,w1)
            float f[8] = {f0.x, f0.y, f0.z, f0.w, f1.x, f1.y, f1.z, f1.w};
            float m[8] = {w1.w, w1.z, w1.y, w1.x, w0.w, w0.z, w0.y, w0.x};
            const float* ccp = (const float*)(smem + SM_COSC) + c * BK + half * 8;
            uint32_t up[4], vp[4];
#pragma unroll
            for (int i = 0; i < 4; ++i) {
                const float wA = __fmaf_rn(-A2, ccp[2 * i], A1);
                const float wB = __fmaf_rn(-A2, ccp[2 * i + 1], A1);
                const float uA = wA * (f[2 * i] + m[2 * i]);
                const float uB = wB * (f[2 * i + 1] + m[2 * i + 1]);
                const float vA = wA * (f[2 * i] - m[2 * i]);
                const float vB = wB * (f[2 * i + 1] - m[2 * i + 1]);
                const __half2 uh = __floats2half2_rn(uA, uB);
                const __half2 vh = __floats2half2_rn(vA, vB);
                up[i] = *(const uint32_t*)&uh;
                vp[i] = *(const uint32_t*)&vh;
            }
            const uint32_t ua = sbase + SM_A + cr * AP + half * 16;
            asm volatile("st.shared.v4.b32 [%0], {%1,%2,%3,%4};"
                         :: "r"(ua), "r"(up[0]), "r"(up[1]), "r"(up[2]), "r"(up[3]));
            asm volatile("st.shared.v4.b32 [%0], {%1,%2,%3,%4};"
                         :: "r"(ua + AMAT), "r"(vp[0]), "r"(vp[1]), "r"(vp[2]), "r"(vp[3]));
        }
        __syncthreads();   // u,v tiles ready

        // ---- MMA on chunk c (K=16, one k-step) ----
        const uint32_t stg = sbase + SM_STG + (c % NSTAGE) * STAGE_B;
        const int krow = ((g8 & 1) << 3) + lr;
        const uint32_t bd = stg + 2 * XBLK + krow * BP + wn * 32 + ((g8 >> 1) << 4);
        uint32_t bC[4], bS[4];
        LDSM4T(bC, bd);
        LDSM4T(bS, bd + BMAT);
#pragma unroll
        for (int mt = 0; mt < 4; ++mt) {
            const int row = wm * 64 + mt * 16 + ((g8 & 1) << 3) + lr;
            const uint32_t ad = sbase + SM_A + row * AP + ((g8 >> 1) << 4);
            uint32_t aU[4], aV[4];
            LDSM4(aU, ad);
            LDSM4(aV, ad + AMAT);
#pragma unroll
            for (int nt = 0; nt < 2; ++nt) {
                MMA16816(accR[mt][nt], aU, bC[nt * 2], bC[nt * 2 + 1]);
                MMA16816(accI[mt][nt], aV, bS[nt * 2], bS[nt * 2 + 1]);
            }
        }
    }

    // ---- epilogue: magnitude; store column k and its mirror 511-k ----
#pragma unroll
    for (int mt = 0; mt < 4; ++mt) {
#pragma unroll
        for (int nt = 0; nt < 2; ++nt) {
            const int r0 = row0 + wm * 64 + mt * 16 + (lid >> 2);
            const int cc = col0 + wn * 16 + nt * 8 + (lid & 3) * 2;
            float2 o0, o1;
            o0.x = sqrtf(fmaf(accR[mt][nt][0], accR[mt][nt][0],
                              accI[mt][nt][0] * accI[mt][nt][0]));
            o0.y = sqrtf(fmaf(accR[mt][nt][1], accR[mt][nt][1],
                              accI[mt][nt][1] * accI[mt][nt][1]));
            o1.x = sqrtf(fmaf(accR[mt][nt][2], accR[mt][nt][2],
                              accI[mt][nt][2] * accI[mt][nt][2]));
            o1.y = sqrtf(fmaf(accR[mt][nt][3], accR[mt][nt][3],
                              accI[mt][nt][3] * accI[mt][nt][3]));
            float* row_a = out + (size_t)r0 * K_;
            float* row_b = out + (size_t)(r0 + 8) * K_;
            *(float2*)(row_a + cc) = o0;
            *(float2*)(row_b + cc) = o1;
            float2 m0 = {o0.y, o0.x};
            float2 m1 = {o1.y, o1.x};
            *(float2*)(row_a + 510 - cc) = m0;
            *(float2*)(row_b + 510 - cc) = m1;
        }
    }
}

// ---------------------------------------------------------------------------
extern "C" void kernel_launch(void* const* d_in, const int* in_sizes, int n_in,
                              void* d_out, int out_size) {
    const float* x     = (const float*)d_in[0];  // (N, D, L)
    const float* a     = (const float*)d_in[1];  // (D,)
    const float* sigma = (const float*)d_in[2];  // (D,)
    float* out = (float*)d_out;                  // (N, D, K)

    precompute_kernel<<<(LH * KH + 255) / 256, 256>>>(a, sigma);

    static bool attr_set = false;
    if (!attr_set) {
        cudaFuncSetAttribute(spectro_fused_kernel,
                             cudaFuncAttributeMaxDynamicSharedMemorySize, SMEM_TOTAL);
        attr_set = true;
    }
    dim3 grid(KH / 64, M_ / 128);   // (4, 512)
    spectro_fused_kernel<<<grid, 256, SMEM_TOTAL>>>(x, out);
}